// round 12
// baseline (speedup 1.0000x reference)
#include <cuda_runtime.h>
#include <cuda_fp16.h>
#include <cstdint>
#include <math.h>

// ---------------- problem constants ----------------
#define B_  8
#define S_  2048
#define D_  1024
#define H_  1024
#define M_  (B_*S_)        // 16384
#define N2_ 2048           // interleaved (k,ph) output width
#define NC_ 16             // chunks per sequence (S_/BM)
#define NCHAIN_ 128        // chains per layer: 16 h-tiles x 8 batches

// ---------------- scratch ----------------
__device__ __half g_Xh [(size_t)M_ * D_];       // fp16 K-permuted layer-0 input
__device__ __half g_X2 [(size_t)M_ * D_];       // fp16 K-permuted layer-1 input
__device__ __half g_Wc [2 * (size_t)N2_ * D_];  // both layers, interleaved+permuted
__device__ int    g_status[2 * NCHAIN_ * NC_];
__device__ float  g_aggA [2 * NCHAIN_ * NC_ * 64];
__device__ float  g_aggB [2 * NCHAIN_ * NC_ * 64];

// ---------------- helpers ----------------
__device__ __forceinline__ uint32_t h2_as_u32(__half2 h) {
    union { __half2 h; uint32_t u; } cvt; cvt.h = h; return cvt.u;
}
__device__ __forceinline__ uint32_t smem_u32(const void* p) {
    uint32_t a;
    asm("{ .reg .u64 t; cvta.to.shared.u64 t, %1; cvt.u32.u64 %0, t; }" : "=r"(a) : "l"(p));
    return a;
}
__device__ __forceinline__ void cpasync16(uint32_t dst, const void* src) {
    asm volatile("cp.async.cg.shared.global [%0], [%1], 16;" :: "r"(dst), "l"(src));
}
#define CP_COMMIT() asm volatile("cp.async.commit_group;" ::: "memory")

__device__ __forceinline__ void mma_fp16(float* c,
    uint32_t a0, uint32_t a1, uint32_t a2, uint32_t a3, uint32_t b0, uint32_t b1)
{
    asm volatile(
        "mma.sync.aligned.m16n8k16.row.col.f32.f16.f16.f32 "
        "{%0,%1,%2,%3}, {%4,%5,%6,%7}, {%8,%9}, {%0,%1,%2,%3};"
        : "+f"(c[0]), "+f"(c[1]), "+f"(c[2]), "+f"(c[3])
        : "r"(a0), "r"(a1), "r"(a2), "r"(a3), "r"(b0), "r"(b1));
}

// one-exp gates: t=e^kv -> a=sigmoid(-kv)=1/(1+t), z=sigmoid(kv)=t/(1+t)
__device__ __forceinline__ void gates2(float kv, float ph, float& a, float& b) {
    float t = __expf(fminf(kv, 80.f));
    float r = __fdividef(1.f, 1.f + t);
    a = r;
    float z = t * r;
    float g = (ph >= 0.f) ? (ph + 0.5f)
                          : __fdividef(1.f, 1.f + __expf(-ph));
    b = z * g;
}

// K-permutation within each 16-group (fragment pairs contiguous)
__device__ __forceinline__ void perm16(const float4 s0, const float4 s1,
                                       const float4 s2, const float4 s3,
                                       uint4& o0, uint4& o1)
{
    o0 = make_uint4(h2_as_u32(__floats2half2_rn(s0.x, s0.y)),
                    h2_as_u32(__floats2half2_rn(s2.x, s2.y)),
                    h2_as_u32(__floats2half2_rn(s0.z, s0.w)),
                    h2_as_u32(__floats2half2_rn(s2.z, s2.w)));
    o1 = make_uint4(h2_as_u32(__floats2half2_rn(s1.x, s1.y)),
                    h2_as_u32(__floats2half2_rn(s3.x, s3.y)),
                    h2_as_u32(__floats2half2_rn(s1.z, s1.w)),
                    h2_as_u32(__floats2half2_rn(s3.z, s3.w)));
}
__device__ __forceinline__ int permcol16(int h) {
    int j = h & 15, q = j >> 1, r = j & 1;
    int slot = (q < 4) ? (2 * q) : (2 * (q - 4) + 1);
    return (h & ~15) | (slot * 2 + r);
}

// ---------------- fp32 -> fp16 + K-permute (also zeroes lookback status) ----
__global__ __launch_bounds__(256) void round_kernel(
    const float4* __restrict__ src, uint4* __restrict__ dst, int n16,
    int* __restrict__ st)
{
    int i = blockIdx.x * 256 + threadIdx.x;
    if (i < 2 * NCHAIN_ * NC_) st[i] = 0;
    if (i >= n16) return;
    uint4 o0, o1;
    perm16(src[4*i], src[4*i+1], src[4*i+2], src[4*i+3], o0, o1);
    dst[2*i] = o0; dst[2*i+1] = o1;
}

// both layers: Wc[l][2h] = perm(Wz_l[h]), Wc[l][2h+1] = perm(Wh_l[h])
__global__ __launch_bounds__(256) void interleave_kernel(
    const float4* __restrict__ Wz, const float4* __restrict__ Wh, uint4* __restrict__ Wc)
{
    int i = blockIdx.x * 256 + threadIdx.x;      // over 2*H_*D_/16 = 131072 groups
    int l = i >> 16;
    int j = i & 65535;
    int h = j >> 6, s = j & 63;
    const float4* wz = Wz + (size_t)l * (H_ * D_ / 4);
    const float4* wh = Wh + (size_t)l * (H_ * D_ / 4);
    uint4 z0, z1, h0, h1;
    perm16(wz[4*j], wz[4*j+1], wz[4*j+2], wz[4*j+3], z0, z1);
    perm16(wh[4*j], wh[4*j+1], wh[4*j+2], wh[4*j+3], h0, h1);
    uint4* base = Wc + (size_t)l * (N2_ * D_ / 8);
    uint4* rz = base + (size_t)(2*h)   * 128 + 2*s;
    uint4* rh = base + (size_t)(2*h+1) * 128 + 2*s;
    rz[0] = z0; rz[1] = z1;
    rh[0] = h0; rh[1] = h1;
}

// ============================================================================
// Fused fp16 GEMM + gates + chunk scan (decoupled lookback) + direct output
// tile 128x128, 4 warps (128 thr), warptile 64x64, BK=32, 4-stage, 2 blk/SM
// LDS/MMA = 0.5 -> smem traffic below tensor-pipe floor
// ============================================================================
#define BM 128
#define BN 128
#define BK 32
#define NT 128                           // threads per block
#define ST 48                            // halfs per smem row (conflict-free)
#define B_OFF (BM * ST)
#define STG_HALFS ((BM + BN) * ST)       // 12288
#define STG_BYTES (STG_HALFS * 2)        // 24576
#define NSTAGE 4
#define GEMM_SMEM (NSTAGE * STG_BYTES)   // 98304
#define GST 136                          // gate tile row stride (floats)

__device__ __forceinline__ void load_stage(
    uint32_t sb, const __half* __restrict__ Ag, const __half* __restrict__ Bg,
    int k0, int tid)
{
    #pragma unroll
    for (int i = 0; i < 4; i++) {        // A: 128 rows x 4 x 16B
        int s = tid + i * NT;
        int r = s >> 2, c = (s & 3) << 3;
        cpasync16(sb + (uint32_t)(r * ST + c) * 2, Ag + (size_t)r * D_ + k0 + c);
    }
    #pragma unroll
    for (int i = 0; i < 4; i++) {        // B: 128 rows x 4 x 16B
        int s = tid + i * NT;
        int r = s >> 2, c = (s & 3) << 3;
        cpasync16(sb + (uint32_t)(B_OFF + r * ST + c) * 2, Bg + (size_t)r * D_ + k0 + c);
    }
    CP_COMMIT();
}

template<int MODE>   // 0: fp16 K-permuted out (next layer); 1: fp32 out
__global__ __launch_bounds__(NT, 2) void gemm_fused_kernel(
    const __half* __restrict__ X, const __half* __restrict__ Wc,
    const float* __restrict__ bz, const float* __restrict__ bh,
    int* __restrict__ status, float* __restrict__ aggA, float* __restrict__ aggB,
    __half* __restrict__ outH, float* __restrict__ outF)
{
    extern __shared__ __align__(16) char smraw[];
    __half* sm = (__half*)smraw;
    const uint32_t sb = smem_u32(sm);
    const int tid = threadIdx.x;
    const int lane = tid & 31, wid = tid >> 5;   // 4 warps
    const int g = lane >> 2, tg = lane & 3;
    const int wm = (wid >> 1) * 64;      // 0 / 64
    const int wn = (wid & 1) * 64;       // 0 / 64
    const int bm = blockIdx.y * BM;
    const int bn = blockIdx.x * BN;

    const __half* Ag = X  + (size_t)bm * D_;
    const __half* Bg = Wc + (size_t)bn * D_;

    float c[4][8][4];
    #pragma unroll
    for (int mt = 0; mt < 4; mt++)
        #pragma unroll
        for (int nt = 0; nt < 8; nt++)
            #pragma unroll
            for (int r = 0; r < 4; r++) c[mt][nt][r] = 0.f;

    load_stage(sb,                 Ag, Bg, 0,      tid);
    load_stage(sb + STG_BYTES,     Ag, Bg, BK,     tid);
    load_stage(sb + 2 * STG_BYTES, Ag, Bg, 2 * BK, tid);

    const int NK = D_ / BK;   // 32
    for (int kt = 0; kt < NK; kt++) {
        asm volatile("cp.async.wait_group 2;" ::: "memory");
        __syncthreads();
        if (kt + 3 < NK)
            load_stage(sb + (uint32_t)((kt + 3) & 3) * STG_BYTES,
                       Ag, Bg, (kt + 3) * BK, tid);
        else
            CP_COMMIT();

        const __half* As = sm + (kt & 3) * STG_HALFS;
        const __half* Bs = As + B_OFF;

        #pragma unroll
        for (int ks = 0; ks < 2; ks++) {
            const int kb = ks * 16 + 4 * tg;
            uint2 alo[4], ahi[4], bf[8];
            #pragma unroll
            for (int mt = 0; mt < 4; mt++) {
                const int m = wm + mt * 16 + g;
                alo[mt] = *(const uint2*)&As[m * ST + kb];
                ahi[mt] = *(const uint2*)&As[(m + 8) * ST + kb];
            }
            #pragma unroll
            for (int nt = 0; nt < 8; nt++) {
                const int n = wn + nt * 8 + g;
                bf[nt] = *(const uint2*)&Bs[n * ST + kb];
            }
            #pragma unroll
            for (int mt = 0; mt < 4; mt++)
                #pragma unroll
                for (int nt = 0; nt < 8; nt++)
                    mma_fp16(c[mt][nt], alo[mt].x, ahi[mt].x, alo[mt].y, ahi[mt].y,
                             bf[nt].x, bf[nt].y);
        }
    }

    // ---------- epilogue: gates -> interleaved smem tile sg[t][2h|2h+1] ----------
    __syncthreads();
    float* sg   = (float*)smraw;          // [128][GST], (a,b) pairs at 2*col
    float* segA = sg + BM * GST;          // [2][64]
    float* segB = segA + 128;
    float* shst = segB + 128;             // [64]

    const int hbase = bn >> 1;
    #pragma unroll
    for (int nt = 0; nt < 8; nt++) {
        const int hl = (wn >> 1) + nt * 4 + tg;     // 0..63
        const float bzv = bz[hbase + hl], bhv = bh[hbase + hl];
        #pragma unroll
        for (int mt = 0; mt < 4; mt++) {
            const int t0 = wm + mt * 16 + g;
            float a0, b0, a1, b1;
            gates2(c[mt][nt][0] + bzv, c[mt][nt][1] + bhv, a0, b0);
            gates2(c[mt][nt][2] + bzv, c[mt][nt][3] + bhv, a1, b1);
            *(float2*)&sg[t0 * GST + 2 * hl]       = make_float2(a0, b0);
            *(float2*)&sg[(t0 + 8) * GST + 2 * hl] = make_float2(a1, b1);
        }
    }
    __syncthreads();

    // ---------- segment compose: 2 threads/column, 64 steps each ----------
    const int batch = blockIdx.y >> 4;
    const int chunk = blockIdx.y & 15;
    const int chain = blockIdx.x * B_ + batch;
    const int sidx  = chain * NC_ + chunk;

    const int col = tid & 63;
    const int seg = tid >> 6;             // 0..1; rows [64*seg, 64*seg+64)
    const int tseg = seg * 64;

    {
        float A = 1.f, Bv = 0.f;
        #pragma unroll 4
        for (int t = 0; t < 64; t++) {
            float2 v = *(const float2*)&sg[(tseg + t) * GST + 2 * col];
            Bv = fmaf(v.x, Bv, v.y);
            A *= v.x;
        }
        segA[seg * 64 + col] = A;
        segB[seg * 64 + col] = Bv;
    }
    __syncthreads();

    // ---------- combine + publish chunk aggregate (seg 0 threads) ----------
    if (seg == 0) {
        float A1 = segA[64 + col], B1 = segB[64 + col];
        float Ac = segA[col], Bc = segB[col];
        aggA[(size_t)sidx * 64 + col] = A1 * Ac;
        aggB[(size_t)sidx * 64 + col] = fmaf(A1, Bc, B1);
        __threadfence();
    }
    __syncthreads();
    if (tid == 0) atomicExch(&status[sidx], 1);

    // ---------- decoupled lookback (seg 0 threads) ----------
    if (seg == 0) {
        float Ar = 1.f, Br = 0.f;
        for (int p = chunk - 1; p >= 0; p--) {
            const int pidx = chain * NC_ + p;
            while (*(volatile int*)(status + pidx) == 0) __nanosleep(32);
            __threadfence();
            float Ap = aggA[(size_t)pidx * 64 + col];
            float Bp = aggB[(size_t)pidx * 64 + col];
            Br = fmaf(Ar, Bp, Br);
            Ar *= Ap;
        }
        shst[col] = fmaf(Ar, 0.5f, Br);   // h at chunk start (h0 = 0.5)
    }
    __syncthreads();

    // ---------- parallel apply + direct global store ----------
    {
        float h = shst[col];
        if (seg == 1) h = fmaf(segA[col], h, segB[col]);

        if (MODE == 0) {
            const int hp = permcol16(hbase + col);
            __half* po = outH + (size_t)(bm + tseg) * H_ + hp;
            #pragma unroll 4
            for (int t = 0; t < 64; t++) {
                float2 v = *(const float2*)&sg[(tseg + t) * GST + 2 * col];
                h = fmaf(v.x, h, v.y);
                po[(size_t)t * H_] = __float2half_rn(h);
            }
        } else {
            float* po = outF + (size_t)(bm + tseg) * H_ + hbase + col;
            #pragma unroll 4
            for (int t = 0; t < 64; t++) {
                float2 v = *(const float2*)&sg[(tseg + t) * GST + 2 * col];
                h = fmaf(v.x, h, v.y);
                po[(size_t)t * H_] = h;
            }
        }
    }
}

// ============================================================================
// launch
// ============================================================================
extern "C" void kernel_launch(void* const* d_in, const int* in_sizes, int n_in,
                              void* d_out, int out_size)
{
    const float* x  = (const float*)d_in[0];
    const float* Wz = (const float*)d_in[1];
    const float* bz = (const float*)d_in[2];
    const float* Wh = (const float*)d_in[3];
    const float* bh = (const float*)d_in[4];
    float* out = (float*)d_out;

    __half *Xh, *X2, *Wc;
    int* st;
    float *aA, *aB;
    cudaGetSymbolAddress((void**)&Xh, g_Xh);
    cudaGetSymbolAddress((void**)&X2, g_X2);
    cudaGetSymbolAddress((void**)&Wc, g_Wc);
    cudaGetSymbolAddress((void**)&st, g_status);
    cudaGetSymbolAddress((void**)&aA, g_aggA);
    cudaGetSymbolAddress((void**)&aB, g_aggB);

    cudaFuncSetAttribute(gemm_fused_kernel<0>,
                         cudaFuncAttributeMaxDynamicSharedMemorySize, GEMM_SMEM);
    cudaFuncSetAttribute(gemm_fused_kernel<1>,
                         cudaFuncAttributeMaxDynamicSharedMemorySize, GEMM_SMEM);

    const size_t LSTRIDE = (size_t)NCHAIN_ * NC_;
    const size_t WL = (size_t)N2_ * D_;            // halfs per layer of Wc
    dim3 gemm_grid(N2_ / BN, M_ / BM);             // (16, 128)

    round_kernel<<<4096, 256>>>((const float4*)x, (uint4*)Xh,
                                (int)((size_t)M_ * D_ / 16), st);
    interleave_kernel<<<512, 256>>>((const float4*)Wz, (const float4*)Wh, (uint4*)Wc);

    gemm_fused_kernel<0><<<gemm_grid, NT, GEMM_SMEM>>>(
        Xh, Wc, bz, bh, st, aA, aB, X2, nullptr);

    gemm_fused_kernel<1><<<gemm_grid, NT, GEMM_SMEM>>>(
        X2, Wc + WL, bz + H_, bh + H_, st + LSTRIDE, aA + LSTRIDE * 64,
        aB + LSTRIDE * 64, nullptr, out);
}

// round 13
// speedup vs baseline: 1.1096x; 1.1096x over previous
#include <cuda_runtime.h>
#include <cuda_fp16.h>
#include <cstdint>
#include <math.h>

// ---------------- problem constants ----------------
#define B_  8
#define S_  2048
#define D_  1024
#define H_  1024
#define M_  (B_*S_)        // 16384
#define N2_ 2048           // interleaved (k,ph) output width
#define NC_ 16             // chunks per sequence (S_/BM)
#define NCHAIN_ 128        // chains per layer: 16 h-tiles x 8 batches

// ---------------- scratch ----------------
__device__ __half g_Xh [(size_t)M_ * D_];       // fp16 K-permuted layer-0 input
__device__ __half g_X2 [(size_t)M_ * D_];       // fp16 K-permuted layer-1 input
__device__ __half g_Wc [2 * (size_t)N2_ * D_];  // both layers, interleaved+permuted
__device__ int    g_status[2 * NCHAIN_ * NC_];
__device__ float  g_aggA [2 * NCHAIN_ * NC_ * 64];
__device__ float  g_aggB [2 * NCHAIN_ * NC_ * 64];

// ---------------- helpers ----------------
__device__ __forceinline__ uint32_t h2_as_u32(__half2 h) {
    union { __half2 h; uint32_t u; } cvt; cvt.h = h; return cvt.u;
}
__device__ __forceinline__ uint32_t smem_u32(const void* p) {
    uint32_t a;
    asm("{ .reg .u64 t; cvta.to.shared.u64 t, %1; cvt.u32.u64 %0, t; }" : "=r"(a) : "l"(p));
    return a;
}
__device__ __forceinline__ void cpasync16(uint32_t dst, const void* src) {
    asm volatile("cp.async.cg.shared.global [%0], [%1], 16;" :: "r"(dst), "l"(src));
}
#define CP_COMMIT() asm volatile("cp.async.commit_group;" ::: "memory")

__device__ __forceinline__ void mma_fp16(float* c,
    uint32_t a0, uint32_t a1, uint32_t a2, uint32_t a3, uint32_t b0, uint32_t b1)
{
    asm volatile(
        "mma.sync.aligned.m16n8k16.row.col.f32.f16.f16.f32 "
        "{%0,%1,%2,%3}, {%4,%5,%6,%7}, {%8,%9}, {%0,%1,%2,%3};"
        : "+f"(c[0]), "+f"(c[1]), "+f"(c[2]), "+f"(c[3])
        : "r"(a0), "r"(a1), "r"(a2), "r"(a3), "r"(b0), "r"(b1));
}

// one-exp gates: t=e^kv -> a=sigmoid(-kv)=1/(1+t), z=sigmoid(kv)=t/(1+t)
__device__ __forceinline__ void gates2(float kv, float ph, float& a, float& b) {
    float t = __expf(fminf(kv, 80.f));
    float r = __fdividef(1.f, 1.f + t);
    a = r;
    float z = t * r;
    float g = (ph >= 0.f) ? (ph + 0.5f)
                          : __fdividef(1.f, 1.f + __expf(-ph));
    b = z * g;
}

// K-permutation within each 16-group (fragment pairs contiguous)
__device__ __forceinline__ void perm16(const float4 s0, const float4 s1,
                                       const float4 s2, const float4 s3,
                                       uint4& o0, uint4& o1)
{
    o0 = make_uint4(h2_as_u32(__floats2half2_rn(s0.x, s0.y)),
                    h2_as_u32(__floats2half2_rn(s2.x, s2.y)),
                    h2_as_u32(__floats2half2_rn(s0.z, s0.w)),
                    h2_as_u32(__floats2half2_rn(s2.z, s2.w)));
    o1 = make_uint4(h2_as_u32(__floats2half2_rn(s1.x, s1.y)),
                    h2_as_u32(__floats2half2_rn(s3.x, s3.y)),
                    h2_as_u32(__floats2half2_rn(s1.z, s1.w)),
                    h2_as_u32(__floats2half2_rn(s3.z, s3.w)));
}
__device__ __forceinline__ int permcol16(int h) {
    int j = h & 15, q = j >> 1, r = j & 1;
    int slot = (q < 4) ? (2 * q) : (2 * (q - 4) + 1);
    return (h & ~15) | (slot * 2 + r);
}

// ---------------- fp32 -> fp16 + K-permute (also zeroes lookback status) ----
__global__ __launch_bounds__(256) void round_kernel(
    const float4* __restrict__ src, uint4* __restrict__ dst, int n16,
    int* __restrict__ st)
{
    int i = blockIdx.x * 256 + threadIdx.x;
    if (i < 2 * NCHAIN_ * NC_) st[i] = 0;
    if (i >= n16) return;
    uint4 o0, o1;
    perm16(src[4*i], src[4*i+1], src[4*i+2], src[4*i+3], o0, o1);
    dst[2*i] = o0; dst[2*i+1] = o1;
}

// both layers: Wc[l][2h] = perm(Wz_l[h]), Wc[l][2h+1] = perm(Wh_l[h])
__global__ __launch_bounds__(256) void interleave_kernel(
    const float4* __restrict__ Wz, const float4* __restrict__ Wh, uint4* __restrict__ Wc)
{
    int i = blockIdx.x * 256 + threadIdx.x;      // over 2*H_*D_/16 = 131072 groups
    int l = i >> 16;
    int j = i & 65535;
    int h = j >> 6, s = j & 63;
    const float4* wz = Wz + (size_t)l * (H_ * D_ / 4);
    const float4* wh = Wh + (size_t)l * (H_ * D_ / 4);
    uint4 z0, z1, h0, h1;
    perm16(wz[4*j], wz[4*j+1], wz[4*j+2], wz[4*j+3], z0, z1);
    perm16(wh[4*j], wh[4*j+1], wh[4*j+2], wh[4*j+3], h0, h1);
    uint4* base = Wc + (size_t)l * (N2_ * D_ / 8);
    uint4* rz = base + (size_t)(2*h)   * 128 + 2*s;
    uint4* rh = base + (size_t)(2*h+1) * 128 + 2*s;
    rz[0] = z0; rz[1] = z1;
    rh[0] = h0; rh[1] = h1;
}

// ============================================================================
// Fused fp16 GEMM + gates + chunk scan (decoupled lookback) + direct output
// tile 128x128, 8 warps (256 thr), warptile 64x32, BK=64, 2-stage, 2 blk/SM
// 16 mainloop iterations (halved barrier/ALU overhead vs BK=32)
// ============================================================================
#define BM 128
#define BN 128
#define BK 64
#define NT 256
#define ST 80                            // halfs per row; 20 words8 = 4 mod 16 -> conflict-free
#define B_OFF (BM * ST)
#define STG_HALFS ((BM + BN) * ST)       // 20480
#define STG_BYTES (STG_HALFS * 2)        // 40960
#define GEMM_SMEM (2 * STG_BYTES)        // 81920
#define GST 136                          // gate tile row stride (floats)

__device__ __forceinline__ void load_stage(
    uint32_t sb, const __half* __restrict__ Ag, const __half* __restrict__ Bg,
    int k0, int tid)
{
    #pragma unroll
    for (int i = 0; i < 4; i++) {        // A: 128 rows x 8 x 16B
        int s = tid + i * NT;
        int r = s >> 3, c = (s & 7) << 3;
        cpasync16(sb + (uint32_t)(r * ST + c) * 2, Ag + (size_t)r * D_ + k0 + c);
    }
    #pragma unroll
    for (int i = 0; i < 4; i++) {        // B: 128 rows x 8 x 16B
        int s = tid + i * NT;
        int r = s >> 3, c = (s & 7) << 3;
        cpasync16(sb + (uint32_t)(B_OFF + r * ST + c) * 2, Bg + (size_t)r * D_ + k0 + c);
    }
    CP_COMMIT();
}

template<int MODE>   // 0: fp16 K-permuted out (next layer); 1: fp32 out
__global__ __launch_bounds__(NT, 2) void gemm_fused_kernel(
    const __half* __restrict__ X, const __half* __restrict__ Wc,
    const float* __restrict__ bz, const float* __restrict__ bh,
    int* __restrict__ status, float* __restrict__ aggA, float* __restrict__ aggB,
    __half* __restrict__ outH, float* __restrict__ outF)
{
    extern __shared__ __align__(16) char smraw[];
    __half* sm = (__half*)smraw;
    const uint32_t sb = smem_u32(sm);
    const int tid = threadIdx.x;
    const int lane = tid & 31, wid = tid >> 5;   // 8 warps
    const int g = lane >> 2, tg = lane & 3;
    const int wm = (wid >> 2) * 64;      // 0 / 64
    const int wn = (wid & 3) * 32;       // 0 / 32 / 64 / 96
    const int bm = blockIdx.y * BM;
    const int bn = blockIdx.x * BN;

    const __half* Ag = X  + (size_t)bm * D_;
    const __half* Bg = Wc + (size_t)bn * D_;

    float c[4][4][4];
    #pragma unroll
    for (int mt = 0; mt < 4; mt++)
        #pragma unroll
        for (int nt = 0; nt < 4; nt++)
            #pragma unroll
            for (int r = 0; r < 4; r++) c[mt][nt][r] = 0.f;

    load_stage(sb, Ag, Bg, 0, tid);      // prologue: stage 0

    const int NK = D_ / BK;   // 16
    for (int kt = 0; kt < NK; kt++) {
        asm volatile("cp.async.wait_group 0;" ::: "memory");   // stage kt ready
        __syncthreads();     // also: all warps done reading buffer (kt+1)&1 (from kt-1)
        if (kt + 1 < NK)
            load_stage(sb + (uint32_t)((kt + 1) & 1) * STG_BYTES,
                       Ag, Bg, (kt + 1) * BK, tid);            // overlaps compute(kt)

        const __half* As = sm + (kt & 1) * STG_HALFS;
        const __half* Bs = As + B_OFF;

        #pragma unroll
        for (int ks = 0; ks < 4; ks++) {              // 4 k16-groups per BK=64
            const int kb = ks * 16 + 4 * tg;
            uint2 alo[4], ahi[4], bf[4];
            #pragma unroll
            for (int mt = 0; mt < 4; mt++) {
                const int m = wm + mt * 16 + g;
                alo[mt] = *(const uint2*)&As[m * ST + kb];
                ahi[mt] = *(const uint2*)&As[(m + 8) * ST + kb];
            }
            #pragma unroll
            for (int nt = 0; nt < 4; nt++) {
                const int n = wn + nt * 8 + g;
                bf[nt] = *(const uint2*)&Bs[n * ST + kb];
            }
            #pragma unroll
            for (int mt = 0; mt < 4; mt++)
                #pragma unroll
                for (int nt = 0; nt < 4; nt++)
                    mma_fp16(c[mt][nt], alo[mt].x, ahi[mt].x, alo[mt].y, ahi[mt].y,
                             bf[nt].x, bf[nt].y);
        }
    }

    // ---------- epilogue: gates -> interleaved smem tile sg[t][2h|2h+1] ----------
    __syncthreads();
    float* sg   = (float*)smraw;          // [128][GST], (a,b) pairs at 2*col
    float* segA = sg + BM * GST;          // [4][64]
    float* segB = segA + 256;
    float* shst = segB + 256;             // [64]

    const int hbase = bn >> 1;
    #pragma unroll
    for (int nt = 0; nt < 4; nt++) {
        const int hl = (wn >> 1) + nt * 4 + tg;     // 0..63
        const float bzv = bz[hbase + hl], bhv = bh[hbase + hl];
        #pragma unroll
        for (int mt = 0; mt < 4; mt++) {
            const int t0 = wm + mt * 16 + g;
            float a0, b0, a1, b1;
            gates2(c[mt][nt][0] + bzv, c[mt][nt][1] + bhv, a0, b0);
            gates2(c[mt][nt][2] + bzv, c[mt][nt][3] + bhv, a1, b1);
            *(float2*)&sg[t0 * GST + 2 * hl]       = make_float2(a0, b0);
            *(float2*)&sg[(t0 + 8) * GST + 2 * hl] = make_float2(a1, b1);
        }
    }
    __syncthreads();

    // ---------- segment compose: 4 threads/column, 32 steps each ----------
    const int batch = blockIdx.y >> 4;
    const int chunk = blockIdx.y & 15;
    const int chain = blockIdx.x * B_ + batch;
    const int sidx  = chain * NC_ + chunk;

    const int col = tid & 63;
    const int seg = tid >> 6;             // 0..3
    const int tseg = seg * 32;

    {
        float A = 1.f, Bv = 0.f;
        #pragma unroll 4
        for (int t = 0; t < 32; t++) {
            float2 v = *(const float2*)&sg[(tseg + t) * GST + 2 * col];
            Bv = fmaf(v.x, Bv, v.y);
            A *= v.x;
        }
        segA[seg * 64 + col] = A;
        segB[seg * 64 + col] = Bv;
    }
    __syncthreads();

    // ---------- combine + publish chunk aggregate (seg 0 threads) ----------
    if (seg == 0) {
        float Ac = segA[col], Bc = segB[col];
        #pragma unroll
        for (int s = 1; s < 4; s++) {
            float As_ = segA[s * 64 + col], Bs_ = segB[s * 64 + col];
            Bc = fmaf(As_, Bc, Bs_);
            Ac *= As_;
        }
        aggA[(size_t)sidx * 64 + col] = Ac;
        aggB[(size_t)sidx * 64 + col] = Bc;
        __threadfence();
    }
    __syncthreads();
    if (tid == 0) atomicExch(&status[sidx], 1);

    // ---------- decoupled lookback (seg 0 threads) ----------
    if (seg == 0) {
        float Ar = 1.f, Br = 0.f;
        for (int p = chunk - 1; p >= 0; p--) {
            const int pidx = chain * NC_ + p;
            while (*(volatile int*)(status + pidx) == 0) __nanosleep(32);
            __threadfence();
            float Ap = aggA[(size_t)pidx * 64 + col];
            float Bp = aggB[(size_t)pidx * 64 + col];
            Br = fmaf(Ar, Bp, Br);
            Ar *= Ap;
        }
        shst[col] = fmaf(Ar, 0.5f, Br);   // h at chunk start (h0 = 0.5)
    }
    __syncthreads();

    // ---------- parallel apply + direct global store ----------
    {
        float h = shst[col];
        #pragma unroll
        for (int s = 0; s < 4; s++)
            if (s < seg) h = fmaf(segA[s * 64 + col], h, segB[s * 64 + col]);

        if (MODE == 0) {
            const int hp = permcol16(hbase + col);
            __half* po = outH + (size_t)(bm + tseg) * H_ + hp;
            #pragma unroll 4
            for (int t = 0; t < 32; t++) {
                float2 v = *(const float2*)&sg[(tseg + t) * GST + 2 * col];
                h = fmaf(v.x, h, v.y);
                po[(size_t)t * H_] = __float2half_rn(h);
            }
        } else {
            float* po = outF + (size_t)(bm + tseg) * H_ + hbase + col;
            #pragma unroll 4
            for (int t = 0; t < 32; t++) {
                float2 v = *(const float2*)&sg[(tseg + t) * GST + 2 * col];
                h = fmaf(v.x, h, v.y);
                po[(size_t)t * H_] = h;
            }
        }
    }
}

// ============================================================================
// launch
// ============================================================================
extern "C" void kernel_launch(void* const* d_in, const int* in_sizes, int n_in,
                              void* d_out, int out_size)
{
    const float* x  = (const float*)d_in[0];
    const float* Wz = (const float*)d_in[1];
    const float* bz = (const float*)d_in[2];
    const float* Wh = (const float*)d_in[3];
    const float* bh = (const float*)d_in[4];
    float* out = (float*)d_out;

    __half *Xh, *X2, *Wc;
    int* st;
    float *aA, *aB;
    cudaGetSymbolAddress((void**)&Xh, g_Xh);
    cudaGetSymbolAddress((void**)&X2, g_X2);
    cudaGetSymbolAddress((void**)&Wc, g_Wc);
    cudaGetSymbolAddress((void**)&st, g_status);
    cudaGetSymbolAddress((void**)&aA, g_aggA);
    cudaGetSymbolAddress((void**)&aB, g_aggB);

    cudaFuncSetAttribute(gemm_fused_kernel<0>,
                         cudaFuncAttributeMaxDynamicSharedMemorySize, GEMM_SMEM);
    cudaFuncSetAttribute(gemm_fused_kernel<1>,
                         cudaFuncAttributeMaxDynamicSharedMemorySize, GEMM_SMEM);

    const size_t LSTRIDE = (size_t)NCHAIN_ * NC_;
    const size_t WL = (size_t)N2_ * D_;            // halfs per layer of Wc
    dim3 gemm_grid(N2_ / BN, M_ / BM);             // (16, 128)

    round_kernel<<<4096, 256>>>((const float4*)x, (uint4*)Xh,
                                (int)((size_t)M_ * D_ / 16), st);
    interleave_kernel<<<512, 256>>>((const float4*)Wz, (const float4*)Wh, (uint4*)Wc);

    gemm_fused_kernel<0><<<gemm_grid, NT, GEMM_SMEM>>>(
        Xh, Wc, bz, bh, st, aA, aB, X2, nullptr);

    gemm_fused_kernel<1><<<gemm_grid, NT, GEMM_SMEM>>>(
        X2, Wc + WL, bz + H_, bh + H_, st + LSTRIDE, aA + LSTRIDE * 64,
        aB + LSTRIDE * 64, nullptr, out);
}

// round 14
// speedup vs baseline: 1.1872x; 1.0699x over previous
#include <cuda_runtime.h>
#include <cuda_fp16.h>
#include <cstdint>
#include <math.h>

// ---------------- problem constants ----------------
#define B_  8
#define S_  2048
#define D_  1024
#define H_  1024
#define M_  (B_*S_)        // 16384
#define N2_ 2048           // interleaved (k,ph) output width
#define NC_ 16             // chunks per sequence (S_/BM)
#define NCHAIN_ 128        // chains per layer: 16 h-tiles x 8 batches
#define LSTRIDE (NCHAIN_ * NC_)   // 2048 lookback slots per layer

// ---------------- scratch ----------------
__device__ __half  g_Xh [(size_t)M_ * D_];       // fp16 K-permuted layer-0 input
__device__ __half  g_X2 [(size_t)M_ * D_];       // fp16 K-permuted layer-1 input
__device__ __half  g_Wc [2 * (size_t)N2_ * D_];  // both layers, interleaved+permuted
__device__ int     g_status[2 * LSTRIDE];
__device__ float2  g_agg   [2 * LSTRIDE * 64];
__device__ int     g_rowcnt[NCHAIN_];            // layer-0 -> layer-1 row readiness

// ---------------- helpers ----------------
__device__ __forceinline__ uint32_t h2_as_u32(__half2 h) {
    union { __half2 h; uint32_t u; } cvt; cvt.h = h; return cvt.u;
}
__device__ __forceinline__ uint32_t smem_u32(const void* p) {
    uint32_t a;
    asm("{ .reg .u64 t; cvta.to.shared.u64 t, %1; cvt.u32.u64 %0, t; }" : "=r"(a) : "l"(p));
    return a;
}
__device__ __forceinline__ void cpasync16(uint32_t dst, const void* src) {
    asm volatile("cp.async.cg.shared.global [%0], [%1], 16;" :: "r"(dst), "l"(src));
}
#define CP_COMMIT() asm volatile("cp.async.commit_group;" ::: "memory")

__device__ __forceinline__ void mma_fp16(float* c,
    uint32_t a0, uint32_t a1, uint32_t a2, uint32_t a3, uint32_t b0, uint32_t b1)
{
    asm volatile(
        "mma.sync.aligned.m16n8k16.row.col.f32.f16.f16.f32 "
        "{%0,%1,%2,%3}, {%4,%5,%6,%7}, {%8,%9}, {%0,%1,%2,%3};"
        : "+f"(c[0]), "+f"(c[1]), "+f"(c[2]), "+f"(c[3])
        : "r"(a0), "r"(a1), "r"(a2), "r"(a3), "r"(b0), "r"(b1));
}

// one-exp gates: t=e^kv -> a=sigmoid(-kv)=1/(1+t), z=sigmoid(kv)=t/(1+t)
__device__ __forceinline__ void gates2(float kv, float ph, float& a, float& b) {
    float t = __expf(fminf(kv, 80.f));
    float r = __fdividef(1.f, 1.f + t);
    a = r;
    float z = t * r;
    float g = (ph >= 0.f) ? (ph + 0.5f)
                          : __fdividef(1.f, 1.f + __expf(-ph));
    b = z * g;
}

// K-permutation within each 16-group (fragment pairs contiguous)
__device__ __forceinline__ void perm16(const float4 s0, const float4 s1,
                                       const float4 s2, const float4 s3,
                                       uint4& o0, uint4& o1)
{
    o0 = make_uint4(h2_as_u32(__floats2half2_rn(s0.x, s0.y)),
                    h2_as_u32(__floats2half2_rn(s2.x, s2.y)),
                    h2_as_u32(__floats2half2_rn(s0.z, s0.w)),
                    h2_as_u32(__floats2half2_rn(s2.z, s2.w)));
    o1 = make_uint4(h2_as_u32(__floats2half2_rn(s1.x, s1.y)),
                    h2_as_u32(__floats2half2_rn(s3.x, s3.y)),
                    h2_as_u32(__floats2half2_rn(s1.z, s1.w)),
                    h2_as_u32(__floats2half2_rn(s3.z, s3.w)));
}
__device__ __forceinline__ int permcol16(int h) {
    int j = h & 15, q = j >> 1, r = j & 1;
    int slot = (q < 4) ? (2 * q) : (2 * (q - 4) + 1);
    return (h & ~15) | (slot * 2 + r);
}

// ---------------- prep: status/rowcnt zero + X convert + W interleave ----------
#define NX16 ((int)((size_t)M_ * D_ / 16))        // 1048576
__global__ __launch_bounds__(256) void prep_kernel(
    const float4* __restrict__ x,
    const float4* __restrict__ Wz, const float4* __restrict__ Wh,
    uint4* __restrict__ Xh, uint4* __restrict__ Wc,
    int* __restrict__ st, int* __restrict__ rowcnt)
{
    int i = blockIdx.x * 256 + threadIdx.x;
    if (i < 2 * LSTRIDE) st[i] = 0;
    if (i < NCHAIN_) rowcnt[i] = 0;
    if (i < NX16) {
        uint4 o0, o1;
        perm16(x[4*i], x[4*i+1], x[4*i+2], x[4*i+3], o0, o1);
        Xh[2*i] = o0; Xh[2*i+1] = o1;
    } else {
        int j = i - NX16;
        if (j >= 131072) return;
        int l = j >> 16;
        int jj = j & 65535;
        int h = jj >> 6, s = jj & 63;
        const float4* wz = Wz + (size_t)l * (H_ * D_ / 4);
        const float4* wh = Wh + (size_t)l * (H_ * D_ / 4);
        uint4 z0, z1, h0, h1;
        perm16(wz[4*jj], wz[4*jj+1], wz[4*jj+2], wz[4*jj+3], z0, z1);
        perm16(wh[4*jj], wh[4*jj+1], wh[4*jj+2], wh[4*jj+3], h0, h1);
        uint4* base = Wc + (size_t)l * (N2_ * D_ / 8);
        uint4* rz = base + (size_t)(2*h)   * 128 + 2*s;
        uint4* rh = base + (size_t)(2*h+1) * 128 + 2*s;
        rz[0] = z0; rz[1] = z1;
        rh[0] = h0; rh[1] = h1;
    }
}

// ============================================================================
// Single-launch dual-layer fused GEMM + gates + chunk scan + output
// tile 128x128, 8 warps, warptile 64x32, BK=64, 2-stage, 2 blk/SM
// layer = bid>=2048; layer-1 waits on per-row completion counters
// ============================================================================
#define BM 128
#define BN 128
#define BK 64
#define NT 256
#define ST 80                            // halfs/row; 20 words8 = 4 mod 16 -> conflict-free
#define B_OFF (BM * ST)
#define STG_HALFS ((BM + BN) * ST)       // 20480
#define STG_BYTES (STG_HALFS * 2)        // 40960
#define GEMM_SMEM (2 * STG_BYTES)        // 81920
#define GST 136                          // gate tile row stride (floats)

__device__ __forceinline__ void loadA_stage(
    uint32_t sb, const __half* __restrict__ Ag, int k0, int tid)
{
    #pragma unroll
    for (int i = 0; i < 4; i++) {
        int s = tid + i * NT;
        int r = s >> 3, c = (s & 7) << 3;
        cpasync16(sb + (uint32_t)(r * ST + c) * 2, Ag + (size_t)r * D_ + k0 + c);
    }
}
__device__ __forceinline__ void loadB_stage(
    uint32_t sb, const __half* __restrict__ Bg, int k0, int tid)
{
    #pragma unroll
    for (int i = 0; i < 4; i++) {
        int s = tid + i * NT;
        int r = s >> 3, c = (s & 7) << 3;
        cpasync16(sb + (uint32_t)(B_OFF + r * ST + c) * 2, Bg + (size_t)r * D_ + k0 + c);
    }
}

__global__ __launch_bounds__(NT, 2) void gemm_fused_kernel(
    const __half* __restrict__ Xh, const __half* __restrict__ X2g,
    const __half* __restrict__ Wc,
    const float* __restrict__ bz, const float* __restrict__ bh,
    int* __restrict__ status, float2* __restrict__ agg,
    int* __restrict__ rowcnt,
    __half* __restrict__ outH, float* __restrict__ outF)
{
    extern __shared__ __align__(16) char smraw[];
    __half* sm = (__half*)smraw;
    const uint32_t sb = smem_u32(sm);
    const int tid = threadIdx.x;
    const int lane = tid & 31, wid = tid >> 5;
    const int g = lane >> 2, tg = lane & 3;
    const int wm = (wid >> 2) * 64;      // 0 / 64
    const int wn = (wid & 3) * 32;       // 0 / 32 / 64 / 96
    const int bid = blockIdx.x;
    const int layer = bid >> 11;         // 0..1
    const int rem = bid & 2047;
    const int by = rem >> 4;             // 0..127 (batch*16 + chunk)
    const int bx = rem & 15;             // h-tile
    const int bm = by * BM;
    const int bn = bx * BN;

    const __half* Xin = layer ? X2g : Xh;
    const __half* Ag = Xin + (size_t)bm * D_;
    const __half* Bg = Wc + (size_t)layer * (N2_ * D_) + (size_t)bn * D_;
    const float* bzp = bz + layer * H_;
    const float* bhp = bh + layer * H_;
    int*    stp  = status + layer * LSTRIDE;
    float2* aggp = agg + (size_t)layer * LSTRIDE * 64;

    float c[4][4][4];
    #pragma unroll
    for (int mt = 0; mt < 4; mt++)
        #pragma unroll
        for (int nt = 0; nt < 4; nt++)
            #pragma unroll
            for (int r = 0; r < 4; r++) c[mt][nt][r] = 0.f;

    // prologue: B first (always ready), then wait for input rows if layer 1
    loadB_stage(sb, Bg, 0, tid);
    if (layer == 1) {
        if (tid == 0)
            while (*(volatile int*)(rowcnt + by) < 16) __nanosleep(64);
        __syncthreads();
        __threadfence();
    }
    loadA_stage(sb, Ag, 0, tid);
    CP_COMMIT();

    const int NK = D_ / BK;   // 16
    for (int kt = 0; kt < NK; kt++) {
        asm volatile("cp.async.wait_group 0;" ::: "memory");
        __syncthreads();
        if (kt + 1 < NK) {
            uint32_t sn = sb + (uint32_t)((kt + 1) & 1) * STG_BYTES;
            loadA_stage(sn, Ag, (kt + 1) * BK, tid);
            loadB_stage(sn, Bg, (kt + 1) * BK, tid);
            CP_COMMIT();
        }

        const __half* As = sm + (kt & 1) * STG_HALFS;
        const __half* Bs = As + B_OFF;

        #pragma unroll
        for (int ks = 0; ks < 4; ks++) {
            const int kb = ks * 16 + 4 * tg;
            uint2 alo[4], ahi[4], bf[4];
            #pragma unroll
            for (int mt = 0; mt < 4; mt++) {
                const int m = wm + mt * 16 + g;
                alo[mt] = *(const uint2*)&As[m * ST + kb];
                ahi[mt] = *(const uint2*)&As[(m + 8) * ST + kb];
            }
            #pragma unroll
            for (int nt = 0; nt < 4; nt++) {
                const int n = wn + nt * 8 + g;
                bf[nt] = *(const uint2*)&Bs[n * ST + kb];
            }
            #pragma unroll
            for (int mt = 0; mt < 4; mt++)
                #pragma unroll
                for (int nt = 0; nt < 4; nt++)
                    mma_fp16(c[mt][nt], alo[mt].x, ahi[mt].x, alo[mt].y, ahi[mt].y,
                             bf[nt].x, bf[nt].y);
        }
    }

    // ---------- epilogue: gates -> interleaved smem tile sg[t][2h|2h+1] ----------
    __syncthreads();
    float* sg   = (float*)smraw;          // [128][GST], (a,b) pairs at 2*col
    float* segA = sg + BM * GST;          // [4][64]
    float* segB = segA + 256;
    float* shst = segB + 256;             // [64]

    const int hbase = bn >> 1;
    #pragma unroll
    for (int nt = 0; nt < 4; nt++) {
        const int hl = (wn >> 1) + nt * 4 + tg;     // 0..63
        const float bzv = bzp[hbase + hl], bhv = bhp[hbase + hl];
        #pragma unroll
        for (int mt = 0; mt < 4; mt++) {
            const int t0 = wm + mt * 16 + g;
            float a0, b0, a1, b1;
            gates2(c[mt][nt][0] + bzv, c[mt][nt][1] + bhv, a0, b0);
            gates2(c[mt][nt][2] + bzv, c[mt][nt][3] + bhv, a1, b1);
            *(float2*)&sg[t0 * GST + 2 * hl]       = make_float2(a0, b0);
            *(float2*)&sg[(t0 + 8) * GST + 2 * hl] = make_float2(a1, b1);
        }
    }
    __syncthreads();

    // ---------- segment compose: 4 threads/column, 32 steps each ----------
    const int batch = by >> 4;
    const int chunk = by & 15;
    const int chain = bx * B_ + batch;
    const int sidx  = chain * NC_ + chunk;

    const int col = tid & 63;
    const int seg = tid >> 6;             // 0..3
    const int tseg = seg * 32;

    {
        float A = 1.f, Bv = 0.f;
        #pragma unroll 4
        for (int t = 0; t < 32; t++) {
            float2 v = *(const float2*)&sg[(tseg + t) * GST + 2 * col];
            Bv = fmaf(v.x, Bv, v.y);
            A *= v.x;
        }
        segA[seg * 64 + col] = A;
        segB[seg * 64 + col] = Bv;
    }
    __syncthreads();

    // ---------- combine + publish chunk aggregate (seg 0 threads) ----------
    if (seg == 0) {
        float Ac = segA[col], Bc = segB[col];
        #pragma unroll
        for (int s = 1; s < 4; s++) {
            float As_ = segA[s * 64 + col], Bs_ = segB[s * 64 + col];
            Bc = fmaf(As_, Bc, Bs_);
            Ac *= As_;
        }
        aggp[(size_t)sidx * 64 + col] = make_float2(Ac, Bc);
        __threadfence();
    }
    __syncthreads();
    if (tid == 0) atomicExch(&stp[sidx], 1);

    // ---------- decoupled lookback (seg 0 threads) ----------
    if (seg == 0) {
        float Ar = 1.f, Br = 0.f;
        for (int p = chunk - 1; p >= 0; p--) {
            const int pidx = chain * NC_ + p;
            while (*(volatile int*)(stp + pidx) == 0) __nanosleep(32);
            __threadfence();
            float2 ab = aggp[(size_t)pidx * 64 + col];
            Br = fmaf(Ar, ab.y, Br);
            Ar *= ab.x;
        }
        shst[col] = fmaf(Ar, 0.5f, Br);   // h at chunk start (h0 = 0.5)
    }
    __syncthreads();

    // ---------- parallel apply + direct global store ----------
    {
        float h = shst[col];
        #pragma unroll
        for (int s = 0; s < 4; s++)
            if (s < seg) h = fmaf(segA[s * 64 + col], h, segB[s * 64 + col]);

        if (layer == 0) {
            const int hp = permcol16(hbase + col);
            __half* po = outH + (size_t)(bm + tseg) * H_ + hp;
            #pragma unroll 4
            for (int t = 0; t < 32; t++) {
                float2 v = *(const float2*)&sg[(tseg + t) * GST + 2 * col];
                h = fmaf(v.x, h, v.y);
                po[(size_t)t * H_] = __float2half_rn(h);
            }
        } else {
            float* po = outF + (size_t)(bm + tseg) * H_ + hbase + col;
            #pragma unroll 4
            for (int t = 0; t < 32; t++) {
                float2 v = *(const float2*)&sg[(tseg + t) * GST + 2 * col];
                h = fmaf(v.x, h, v.y);
                po[(size_t)t * H_] = h;
            }
        }
    }

    // ---------- layer-0: publish row completion for layer 1 ----------
    if (layer == 0) {
        __syncthreads();
        if (tid == 0) {
            __threadfence();
            atomicAdd(&rowcnt[by], 1);
        }
    }
}

// ============================================================================
// launch
// ============================================================================
extern "C" void kernel_launch(void* const* d_in, const int* in_sizes, int n_in,
                              void* d_out, int out_size)
{
    const float* x  = (const float*)d_in[0];
    const float* Wz = (const float*)d_in[1];
    const float* bz = (const float*)d_in[2];
    const float* Wh = (const float*)d_in[3];
    const float* bh = (const float*)d_in[4];
    float* out = (float*)d_out;

    __half *Xh, *X2, *Wc;
    int *st, *rc;
    float2* ag;
    cudaGetSymbolAddress((void**)&Xh, g_Xh);
    cudaGetSymbolAddress((void**)&X2, g_X2);
    cudaGetSymbolAddress((void**)&Wc, g_Wc);
    cudaGetSymbolAddress((void**)&st, g_status);
    cudaGetSymbolAddress((void**)&ag, g_agg);
    cudaGetSymbolAddress((void**)&rc, g_rowcnt);

    cudaFuncSetAttribute(gemm_fused_kernel,
                         cudaFuncAttributeMaxDynamicSharedMemorySize, GEMM_SMEM);

    // prep: 1048576 X-groups + 131072 W-groups -> 4608 blocks
    prep_kernel<<<4608, 256>>>((const float4*)x, (const float4*)Wz,
                               (const float4*)Wh, (uint4*)Xh, (uint4*)Wc, st, rc);

    // both layers in one launch: bids 0..2047 layer 0, 2048..4095 layer 1
    gemm_fused_kernel<<<4096, NT, GEMM_SMEM>>>(
        Xh, X2, Wc, bz, bh, st, ag, rc, X2, out);
}

// round 15
// speedup vs baseline: 1.2343x; 1.0397x over previous
#include <cuda_runtime.h>
#include <cuda_fp16.h>
#include <cstdint>
#include <math.h>

// ---------------- problem constants ----------------
#define B_  8
#define S_  2048
#define D_  1024
#define H_  1024
#define M_  (B_*S_)        // 16384
#define N2_ 2048           // interleaved (k,ph) output width
#define NC_ 16             // chunks per sequence (S_/BM)
#define NCHAIN_ 128        // chains per layer: 16 h-tiles x 8 batches
#define LSTRIDE (NCHAIN_ * NC_)   // 2048 lookback slots per layer

// ---------------- scratch ----------------
__device__ __half  g_Xh [(size_t)M_ * D_];       // fp16 K-permuted layer-0 input
__device__ __half  g_X2 [(size_t)M_ * D_];       // fp16 K-permuted layer-1 input
__device__ __half  g_Wc [2 * (size_t)N2_ * D_];  // both layers, interleaved+permuted
__device__ int     g_status[2 * LSTRIDE];
__device__ float2  g_agg   [2 * LSTRIDE * 64];
__device__ int     g_rowcnt[NCHAIN_];            // layer-0 -> layer-1 row readiness

// ---------------- helpers ----------------
__device__ __forceinline__ uint32_t h2_as_u32(__half2 h) {
    union { __half2 h; uint32_t u; } cvt; cvt.h = h; return cvt.u;
}
__device__ __forceinline__ uint32_t smem_u32(const void* p) {
    uint32_t a;
    asm("{ .reg .u64 t; cvta.to.shared.u64 t, %1; cvt.u32.u64 %0, t; }" : "=r"(a) : "l"(p));
    return a;
}
__device__ __forceinline__ void cpasync16(uint32_t dst, const void* src) {
    asm volatile("cp.async.cg.shared.global [%0], [%1], 16;" :: "r"(dst), "l"(src));
}
#define CP_COMMIT() asm volatile("cp.async.commit_group;" ::: "memory")
#define CP_WAIT0()  asm volatile("cp.async.wait_group 0;" ::: "memory")

__device__ __forceinline__ void mma_fp16(float* c,
    uint32_t a0, uint32_t a1, uint32_t a2, uint32_t a3, uint32_t b0, uint32_t b1)
{
    asm volatile(
        "mma.sync.aligned.m16n8k16.row.col.f32.f16.f16.f32 "
        "{%0,%1,%2,%3}, {%4,%5,%6,%7}, {%8,%9}, {%0,%1,%2,%3};"
        : "+f"(c[0]), "+f"(c[1]), "+f"(c[2]), "+f"(c[3])
        : "r"(a0), "r"(a1), "r"(a2), "r"(a3), "r"(b0), "r"(b1));
}

// one-exp gates: t=e^kv -> a=sigmoid(-kv)=1/(1+t), z=sigmoid(kv)=t/(1+t)
__device__ __forceinline__ void gates2(float kv, float ph, float& a, float& b) {
    float t = __expf(fminf(kv, 80.f));
    float r = __fdividef(1.f, 1.f + t);
    a = r;
    float z = t * r;
    float g = (ph >= 0.f) ? (ph + 0.5f)
                          : __fdividef(1.f, 1.f + __expf(-ph));
    b = z * g;
}

// K-permutation within each 16-group (fragment pairs contiguous)
__device__ __forceinline__ void perm16(const float4 s0, const float4 s1,
                                       const float4 s2, const float4 s3,
                                       uint4& o0, uint4& o1)
{
    o0 = make_uint4(h2_as_u32(__floats2half2_rn(s0.x, s0.y)),
                    h2_as_u32(__floats2half2_rn(s2.x, s2.y)),
                    h2_as_u32(__floats2half2_rn(s0.z, s0.w)),
                    h2_as_u32(__floats2half2_rn(s2.z, s2.w)));
    o1 = make_uint4(h2_as_u32(__floats2half2_rn(s1.x, s1.y)),
                    h2_as_u32(__floats2half2_rn(s3.x, s3.y)),
                    h2_as_u32(__floats2half2_rn(s1.z, s1.w)),
                    h2_as_u32(__floats2half2_rn(s3.z, s3.w)));
}
__device__ __forceinline__ int permcol16(int h) {
    int j = h & 15, q = j >> 1, r = j & 1;
    int slot = (q < 4) ? (2 * q) : (2 * (q - 4) + 1);
    return (h & ~15) | (slot * 2 + r);
}

// ---------------- prep: status/rowcnt zero + X convert + W interleave ----------
#define NX16 ((int)((size_t)M_ * D_ / 16))        // 1048576
__global__ __launch_bounds__(256) void prep_kernel(
    const float4* __restrict__ x,
    const float4* __restrict__ Wz, const float4* __restrict__ Wh,
    uint4* __restrict__ Xh, uint4* __restrict__ Wc,
    int* __restrict__ st, int* __restrict__ rowcnt)
{
    int i = blockIdx.x * 256 + threadIdx.x;
    if (i < 2 * LSTRIDE) st[i] = 0;
    if (i < NCHAIN_) rowcnt[i] = 0;
    if (i < NX16) {
        uint4 o0, o1;
        perm16(x[4*i], x[4*i+1], x[4*i+2], x[4*i+3], o0, o1);
        Xh[2*i] = o0; Xh[2*i+1] = o1;
    } else {
        int j = i - NX16;
        if (j >= 131072) return;
        int l = j >> 16;
        int jj = j & 65535;
        int h = jj >> 6, s = jj & 63;
        const float4* wz = Wz + (size_t)l * (H_ * D_ / 4);
        const float4* wh = Wh + (size_t)l * (H_ * D_ / 4);
        uint4 z0, z1, h0, h1;
        perm16(wz[4*jj], wz[4*jj+1], wz[4*jj+2], wz[4*jj+3], z0, z1);
        perm16(wh[4*jj], wh[4*jj+1], wh[4*jj+2], wh[4*jj+3], h0, h1);
        uint4* base = Wc + (size_t)l * (N2_ * D_ / 8);
        uint4* rz = base + (size_t)(2*h)   * 128 + 2*s;
        uint4* rh = base + (size_t)(2*h+1) * 128 + 2*s;
        rz[0] = z0; rz[1] = z1;
        rh[0] = h0; rh[1] = h1;
    }
}

// ============================================================================
// Single-launch dual-layer fused GEMM + gates + chunk scan + output
// tile 128x128, 8 warps, warptile 64x32, BK=64, 2-stage, 2 blk/SM
// mainloop unrolled x2, loop-carried pointers (no per-iter address math)
// ============================================================================
#define BM 128
#define BN 128
#define BK 64
#define NT 256
#define ST 80                            // halfs/row; 20 words8 = 4 mod 16 -> conflict-free
#define B_OFF (BM * ST)
#define STG_HALFS ((BM + BN) * ST)       // 20480
#define STG_BYTES (STG_HALFS * 2)        // 40960
#define GEMM_SMEM (2 * STG_BYTES)        // 81920
#define GST 136                          // gate tile row stride (floats)

// issue one stage of cp.async (A+B) from loop-carried pointers, then advance
__device__ __forceinline__ void issue_stage(
    uint32_t wA, uint32_t wB, const __half*& ap, const __half*& bp)
{
    #pragma unroll
    for (int i = 0; i < 4; i++)
        cpasync16(wA + (uint32_t)(i * 32 * ST) * 2, ap + (size_t)(i * 32) * D_);
    #pragma unroll
    for (int i = 0; i < 4; i++)
        cpasync16(wB + (uint32_t)(i * 32 * ST) * 2, bp + (size_t)(i * 32) * D_);
    CP_COMMIT();
    ap += BK; bp += BK;
}

// one pipeline step: wait current, prefetch into other, compute current
__device__ __forceinline__ void pipe_step(
    const __half* As, uint32_t wA_other, uint32_t wB_other,
    const __half*& ap, const __half*& bp, bool do_load,
    float c[4][4][4], int wm, int wn, int g, int kb0)
{
    CP_WAIT0();
    __syncthreads();
    if (do_load) issue_stage(wA_other, wB_other, ap, bp);

    const __half* Bs = As + B_OFF;
    #pragma unroll
    for (int ks = 0; ks < 4; ks++) {
        const int kb = ks * 16 + kb0;
        uint2 alo[4], ahi[4], bf[4];
        #pragma unroll
        for (int mt = 0; mt < 4; mt++) {
            const int m = wm + mt * 16 + g;
            alo[mt] = *(const uint2*)&As[m * ST + kb];
            ahi[mt] = *(const uint2*)&As[(m + 8) * ST + kb];
        }
        #pragma unroll
        for (int nt = 0; nt < 4; nt++) {
            const int n = wn + nt * 8 + g;
            bf[nt] = *(const uint2*)&Bs[n * ST + kb];
        }
        #pragma unroll
        for (int mt = 0; mt < 4; mt++)
            #pragma unroll
            for (int nt = 0; nt < 4; nt++)
                mma_fp16(c[mt][nt], alo[mt].x, ahi[mt].x, alo[mt].y, ahi[mt].y,
                         bf[nt].x, bf[nt].y);
    }
}

__global__ __launch_bounds__(NT, 2) void gemm_fused_kernel(
    const __half* __restrict__ Xh, const __half* __restrict__ X2g,
    const __half* __restrict__ Wc,
    const float* __restrict__ bz, const float* __restrict__ bh,
    int* __restrict__ status, float2* __restrict__ agg,
    int* __restrict__ rowcnt,
    __half* __restrict__ outH, float* __restrict__ outF)
{
    extern __shared__ __align__(16) char smraw[];
    __half* sm = (__half*)smraw;
    const uint32_t sb = smem_u32(sm);
    const int tid = threadIdx.x;
    const int lane = tid & 31, wid = tid >> 5;
    const int g = lane >> 2, tg = lane & 3;
    const int kb0 = 4 * tg;
    const int wm = (wid >> 2) * 64;
    const int wn = (wid & 3) * 32;
    const int bid = blockIdx.x;
    const int layer = bid >> 11;
    const int rem = bid & 2047;
    const int by = rem >> 4;
    const int bx = rem & 15;
    const int bm = by * BM;
    const int bn = bx * BN;

    const __half* Xin = layer ? X2g : Xh;
    // loop-carried source pointers (per-thread)
    const int lr = tid >> 3, lc = (tid & 7) << 3;
    const __half* ap = Xin + (size_t)(bm + lr) * D_ + lc;
    const __half* bp = Wc + (size_t)layer * (N2_ * D_) + (size_t)(bn + lr) * D_ + lc;
    // per-thread smem write addresses for the two stages
    const uint32_t wbase = (uint32_t)(lr * ST + lc) * 2;
    const uint32_t wA0 = sb + wbase,              wA1 = wA0 + STG_BYTES;
    const uint32_t wB0 = sb + B_OFF * 2 + wbase,  wB1 = wB0 + STG_BYTES;
    const __half* As0 = sm;
    const __half* As1 = sm + STG_HALFS;

    const float* bzp = bz + layer * H_;
    const float* bhp = bh + layer * H_;
    int*    stp  = status + layer * LSTRIDE;
    float2* aggp = agg + (size_t)layer * LSTRIDE * 64;

    float c[4][4][4];
    #pragma unroll
    for (int mt = 0; mt < 4; mt++)
        #pragma unroll
        for (int nt = 0; nt < 4; nt++)
            #pragma unroll
            for (int r = 0; r < 4; r++) c[mt][nt][r] = 0.f;

    // prologue: wait on layer-0 completion if needed, then stage 0
    if (layer == 1) {
        if (tid == 0)
            while (*(volatile int*)(rowcnt + by) < 16) __nanosleep(64);
        __syncthreads();
        __threadfence();
    }
    issue_stage(wA0, wB0, ap, bp);

    // mainloop: 16 K-tiles, unrolled x2 (8 double-steps)
    #pragma unroll 1
    for (int it = 0; it < 8; it++) {
        pipe_step(As0, wA1, wB1, ap, bp, true,        c, wm, wn, g, kb0);
        pipe_step(As1, wA0, wB0, ap, bp, it < 7,      c, wm, wn, g, kb0);
    }

    // ---------- epilogue: gates -> interleaved smem tile sg[t][2h|2h+1] ----------
    __syncthreads();
    float* sg   = (float*)smraw;          // [128][GST], (a,b) pairs at 2*col
    float* segA = sg + BM * GST;          // [4][64]
    float* segB = segA + 256;
    float* shst = segB + 256;             // [64]

    const int hbase = bn >> 1;
    #pragma unroll
    for (int nt = 0; nt < 4; nt++) {
        const int hl = (wn >> 1) + nt * 4 + tg;     // 0..63
        const float bzv = bzp[hbase + hl], bhv = bhp[hbase + hl];
        #pragma unroll
        for (int mt = 0; mt < 4; mt++) {
            const int t0 = wm + mt * 16 + g;
            float a0, b0, a1, b1;
            gates2(c[mt][nt][0] + bzv, c[mt][nt][1] + bhv, a0, b0);
            gates2(c[mt][nt][2] + bzv, c[mt][nt][3] + bhv, a1, b1);
            *(float2*)&sg[t0 * GST + 2 * hl]       = make_float2(a0, b0);
            *(float2*)&sg[(t0 + 8) * GST + 2 * hl] = make_float2(a1, b1);
        }
    }
    __syncthreads();

    // ---------- segment compose: 4 threads/column, 32 steps each ----------
    const int batch = by >> 4;
    const int chunk = by & 15;
    const int chain = bx * B_ + batch;
    const int sidx  = chain * NC_ + chunk;

    const int col = tid & 63;
    const int seg = tid >> 6;             // 0..3
    const int tseg = seg * 32;

    {
        float A = 1.f, Bv = 0.f;
        #pragma unroll 4
        for (int t = 0; t < 32; t++) {
            float2 v = *(const float2*)&sg[(tseg + t) * GST + 2 * col];
            Bv = fmaf(v.x, Bv, v.y);
            A *= v.x;
        }
        segA[seg * 64 + col] = A;
        segB[seg * 64 + col] = Bv;
    }
    __syncthreads();

    // ---------- combine + publish chunk aggregate (seg 0 threads) ----------
    if (seg == 0) {
        float Ac = segA[col], Bc = segB[col];
        #pragma unroll
        for (int s = 1; s < 4; s++) {
            float As_ = segA[s * 64 + col], Bs_ = segB[s * 64 + col];
            Bc = fmaf(As_, Bc, Bs_);
            Ac *= As_;
        }
        aggp[(size_t)sidx * 64 + col] = make_float2(Ac, Bc);
        __threadfence();
    }
    __syncthreads();
    if (tid == 0) atomicExch(&stp[sidx], 1);

    // ---------- decoupled lookback (seg 0 threads) ----------
    if (seg == 0) {
        float Ar = 1.f, Br = 0.f;
        for (int p = chunk - 1; p >= 0; p--) {
            const int pidx = chain * NC_ + p;
            while (*(volatile int*)(stp + pidx) == 0) __nanosleep(32);
            __threadfence();
            float2 ab = aggp[(size_t)pidx * 64 + col];
            Br = fmaf(Ar, ab.y, Br);
            Ar *= ab.x;
        }
        shst[col] = fmaf(Ar, 0.5f, Br);   // h at chunk start (h0 = 0.5)
    }
    __syncthreads();

    // ---------- parallel apply + direct global store ----------
    {
        float h = shst[col];
        #pragma unroll
        for (int s = 0; s < 4; s++)
            if (s < seg) h = fmaf(segA[s * 64 + col], h, segB[s * 64 + col]);

        if (layer == 0) {
            const int hp = permcol16(hbase + col);
            __half* po = outH + (size_t)(bm + tseg) * H_ + hp;
            #pragma unroll 4
            for (int t = 0; t < 32; t++) {
                float2 v = *(const float2*)&sg[(tseg + t) * GST + 2 * col];
                h = fmaf(v.x, h, v.y);
                po[(size_t)t * H_] = __float2half_rn(h);
            }
        } else {
            float* po = outF + (size_t)(bm + tseg) * H_ + hbase + col;
            #pragma unroll 4
            for (int t = 0; t < 32; t++) {
                float2 v = *(const float2*)&sg[(tseg + t) * GST + 2 * col];
                h = fmaf(v.x, h, v.y);
                po[(size_t)t * H_] = h;
            }
        }
    }

    // ---------- layer-0: publish row completion for layer 1 ----------
    if (layer == 0) {
        __syncthreads();
        if (tid == 0) {
            __threadfence();
            atomicAdd(&rowcnt[by], 1);
        }
    }
}

// ============================================================================
// launch
// ============================================================================
extern "C" void kernel_launch(void* const* d_in, const int* in_sizes, int n_in,
                              void* d_out, int out_size)
{
    const float* x  = (const float*)d_in[0];
    const float* Wz = (const float*)d_in[1];
    const float* bz = (const float*)d_in[2];
    const float* Wh = (const float*)d_in[3];
    const float* bh = (const float*)d_in[4];
    float* out = (float*)d_out;

    __half *Xh, *X2, *Wc;
    int *st, *rc;
    float2* ag;
    cudaGetSymbolAddress((void**)&Xh, g_Xh);
    cudaGetSymbolAddress((void**)&X2, g_X2);
    cudaGetSymbolAddress((void**)&Wc, g_Wc);
    cudaGetSymbolAddress((void**)&st, g_status);
    cudaGetSymbolAddress((void**)&ag, g_agg);
    cudaGetSymbolAddress((void**)&rc, g_rowcnt);

    cudaFuncSetAttribute(gemm_fused_kernel,
                         cudaFuncAttributeMaxDynamicSharedMemorySize, GEMM_SMEM);

    prep_kernel<<<4608, 256>>>((const float4*)x, (const float4*)Wz,
                               (const float4*)Wh, (uint4*)Xh, (uint4*)Wc, st, rc);

    gemm_fused_kernel<<<4096, NT, GEMM_SMEM>>>(
        Xh, X2, Wc, bz, bh, st, ag, rc, X2, out);
}